// round 17
// baseline (speedup 1.0000x reference)
#include <cuda_runtime.h>
#include <cuda_fp16.h>
#include <math_constants.h>
#include <cstdint>

// Problem constants
#define BB    32
#define SS    512
#define MM    8
#define HH    512
#define KBIG  1536          // face|fc|img (label folded into pm)
#define DIM1_ 2048
#define WCOLS 2560
#define EPSF  1e-5f

// GEMM tiling: CTA 128x128, warp tile 64x32, 8 warps (256 threads), 2 CTAs/SM
#define GM 128
#define GN 128
#define KC 64                        // fp16 k per chunk = 128 B/row
#define NCH (KBIG / KC)              // 24 chunks
#define A_TILE 16384                 // 128 rows x 128 B
#define B_TILE 16384                 // 128 rows x 128 B
#define STAGE_BYTES (A_TILE + B_TILE)   // 32 KB
#define NSTAGE 3
#define DYN_SMEM (NSTAGE * STAGE_BYTES + 1024)

// Scratch (device globals — no allocation allowed)
__device__ __half g_pb16[(size_t)BB * SS * HH]; // part_base, fp16 (32 MB)
__device__ float g_pm[BB * MM * HH];           // part_mem + label part + b1
__device__ float g_e [BB * MM * SS];           // logits e[b, m*S+s]
__device__ float g_as[BB * SS];                // per-s alpha sums (over m)
__device__ float g_cp[BB * 4 * 512];           // context partials
__device__ __half g_W16[HH * KBIG];            // W1 slice, fp16
__device__ __half g_A16[(size_t)BB * SS * KBIG]; // features, fp16, k-contiguous

__device__ __forceinline__ uint32_t smem_u32(const void* p) {
    return (uint32_t)__cvta_generic_to_shared(p);
}

#define LDMX4(r, addr) \
    asm volatile("ldmatrix.sync.aligned.m8n8.x4.shared.b16 {%0,%1,%2,%3}, [%4];" \
        : "=r"((r)[0]), "=r"((r)[1]), "=r"((r)[2]), "=r"((r)[3]) : "r"(addr))

#define MMA16816(d, a, b0v, b1v) \
    asm volatile("mma.sync.aligned.m16n8k16.row.col.f32.f16.f16.f32 " \
        "{%0,%1,%2,%3}, {%4,%5,%6,%7}, {%8,%9}, {%0,%1,%2,%3};" \
        : "+f"((d)[0]), "+f"((d)[1]), "+f"((d)[2]), "+f"((d)[3]) \
        : "r"((a)[0]), "r"((a)[1]), "r"((a)[2]), "r"((a)[3]), "r"(b0v), "r"(b1v))

#define CPASYNC(dst, src) \
    asm volatile("cp.async.cg.shared.global [%0], [%1], 16;" :: "r"(dst), "l"(src))
#define CPCOMMIT() asm volatile("cp.async.commit_group;" ::: "memory")
#define CPWAIT1()  asm volatile("cp.async.wait_group 1;" ::: "memory")

// 1-MUFU tanh (arch-agnostic PTX, sm_75+)
__device__ __forceinline__ float fast_tanh(float x) {
    float y;
    asm("tanh.approx.f32 %0, %1;" : "=f"(y) : "f"(x));
    return y;
}

// fp32x4 -> fp16x4
__device__ __forceinline__ uint2 cvt4h(float4 v) {
    __half2 h0 = __floats2half2_rn(v.x, v.y);
    __half2 h1 = __floats2half2_rn(v.z, v.w);
    return make_uint2(*(uint32_t*)&h0, *(uint32_t*)&h1);
}

// ---------------------------------------------------------------------------
// Kernel 0 (merged): pm GEMV | W1->fp16 | features->fp16 (block-range split)
// ---------------------------------------------------------------------------
#define W4    (HH * KBIG / 4)                      // 196608 float4s
#define FEAT4 ((size_t)(BB * SS) * (KBIG / 4))     // 6291456 float4s
#define NB_PM ((BB * MM * HH) / 8)
#define NB_W  (W4 / 256)
#define NB_A  ((int)(FEAT4 / 256))

__global__ __launch_bounds__(256)
void setup_kernel(const float* __restrict__ W1, const float* __restrict__ memory,
                  const float* __restrict__ label, const float* __restrict__ b1,
                  const float* __restrict__ face, const float* __restrict__ fc,
                  const float* __restrict__ img)
{
    const int tid = threadIdx.x;
    if (blockIdx.x < NB_PM) {
        const int gw   = (blockIdx.x * 256 + tid) >> 5;
        const int lane = tid & 31;
        const int h  = gw & (HH - 1);
        const int bm = gw >> 9;
        const int b  = bm >> 3;

        const float* __restrict__ wmem = W1 + (size_t)h * WCOLS + DIM1_;
        const float* __restrict__ wlab = W1 + (size_t)h * WCOLS + KBIG;
        const float* __restrict__ mrow = memory + (size_t)bm * HH;
        const float* __restrict__ lrow = label  + (size_t)b * 512;

        float acc = 0.f;
#pragma unroll 4
        for (int d = lane; d < HH; d += 32)
            acc = fmaf(wmem[d], mrow[d], fmaf(wlab[d], lrow[d], acc));
#pragma unroll
        for (int o = 16; o; o >>= 1) acc += __shfl_xor_sync(0xFFFFFFFFu, acc, o);
        if (lane == 0) g_pm[gw] = acc + b1[h];
    } else if (blockIdx.x < NB_PM + NB_W) {
        const int idx = (blockIdx.x - NB_PM) * 256 + tid;
        const int h = idx / (KBIG / 4);
        const int k = (idx % (KBIG / 4)) * 4;
        *(uint2*)&g_W16[h * KBIG + k] = cvt4h(*(const float4*)&W1[(size_t)h * WCOLS + k]);
    } else {
        const size_t idx = (size_t)(blockIdx.x - NB_PM - NB_W) * 256 + tid;
        const size_t r = idx / (KBIG / 4);
        const int    k = (int)(idx % (KBIG / 4)) * 4;
        const int    f = k >> 9;
        const float* src = ((f == 0) ? face : (f == 1 ? fc : img)) + r * 512 + (k & 511);
        *(uint2*)&g_A16[r * KBIG + k] = cvt4h(*(const float4*)src);
    }
}

// ---------------------------------------------------------------------------
// GEMM: pure cp.async mainloop, 3-stage pipeline, one barrier per chunk.
// Stage layout: A16 0 | W16 16K. 256 threads, 2 CTAs/SM. fp16 pb output.
// ---------------------------------------------------------------------------
__device__ __forceinline__ void load_stage(uint32_t sb, int tid,
                                           int rowBase, int colBase, int kt)
{
#pragma unroll
    for (int i = 0; i < 4; i++) {              // A: 128 rows x 8 slots / 256
        const int v   = tid + i * 256;
        const int row = v >> 3;
        const int cs  = v & 7;
        const uint32_t off = (uint32_t)row * 128 + cs * 16;
        const uint32_t sw  = off ^ ((off >> 3) & 0x70);
        const size_t aoff = (size_t)(rowBase + row) * KBIG + kt * KC + cs * 8;
        CPASYNC(sb + sw, (const char*)&g_A16[aoff]);
    }
#pragma unroll
    for (int i = 0; i < 4; i++) {              // W: 128 rows x 8 slots / 256
        const int v   = tid + i * 256;
        const int row = v >> 3;
        const int cs  = v & 7;
        const uint32_t off = (uint32_t)row * 128 + cs * 16;
        const uint32_t sw  = off ^ ((off >> 3) & 0x70);
        const size_t boff = (size_t)(colBase + row) * KBIG + kt * KC + cs * 8;
        CPASYNC(sb + A_TILE + sw, (const char*)&g_W16[boff]);
    }
}

__device__ __forceinline__ void mma_stage(uint32_t sb, float (&d)[4][4][4],
        int mw, int nw, int a_r, int a_kh, int b_r, int b_kh)
{
#pragma unroll
    for (int ks = 0; ks < 4; ks++) {
        const uint32_t kb = (uint32_t)(ks * 2) * 16;

        uint32_t bh[2][4];
#pragma unroll
        for (int p = 0; p < 2; p++) {
            const uint32_t off = (uint32_t)(nw * 32 + p * 16 + b_r) * 128 + kb + b_kh * 16;
            LDMX4(bh[p], sb + A_TILE + (off ^ ((off >> 3) & 0x70)));
        }
        uint32_t ah[4][4];
#pragma unroll
        for (int i = 0; i < 4; i++) {
            const uint32_t off = (uint32_t)(mw * 64 + i * 16 + a_r) * 128 + kb + a_kh * 16;
            LDMX4(ah[i], sb + (off ^ ((off >> 3) & 0x70)));
        }
#pragma unroll
        for (int i = 0; i < 4; i++)
#pragma unroll
            for (int p = 0; p < 2; p++) {
                MMA16816(d[i][2 * p],     ah[i], bh[p][0], bh[p][1]);
                MMA16816(d[i][2 * p + 1], ah[i], bh[p][2], bh[p][3]);
            }
    }
}

__global__ __launch_bounds__(256, 2)
void gemm_pb_mma(void)
{
    extern __shared__ char dynsmem[];
    const uint32_t dynaddr = smem_u32(dynsmem);
    const uint32_t sbase = (dynaddr + 1023) & ~1023u;

    const int tid  = threadIdx.x;
    const int warp = tid >> 5;
    const int lane = tid & 31;
    const int mw = warp >> 2;            // 0..1 : m offset mw*64
    const int nw = warp & 3;             // 0..3 : n offset nw*32
    const int colBase = blockIdx.x * GN;
    const int rowBase = blockIdx.y * GM;

    const int a_r  = lane & 15;
    const int a_kh = lane >> 4;
    const int b_r  = (lane & 7) + ((lane >> 4) << 3);
    const int b_kh = (lane >> 3) & 1;

    float d[4][4][4];
#pragma unroll
    for (int i = 0; i < 4; i++)
#pragma unroll
        for (int j = 0; j < 4; j++)
#pragma unroll
            for (int q = 0; q < 4; q++) d[i][j][q] = 0.f;

    // Prologue: 2 stages in flight
    load_stage(sbase, tid, rowBase, colBase, 0);
    CPCOMMIT();
    load_stage(sbase + STAGE_BYTES, tid, rowBase, colBase, 1);
    CPCOMMIT();

    for (int kt = 0; kt < NCH; kt++) {
        CPWAIT1();
        __syncthreads();
        if (kt + 2 < NCH)
            load_stage(sbase + ((kt + 2) % 3) * STAGE_BYTES, tid, rowBase, colBase, kt + 2);
        CPCOMMIT();
        mma_stage(sbase + (kt % 3) * STAGE_BYTES, d, mw, nw, a_r, a_kh, b_r, b_kh);
    }

    // Epilogue: fragment pairs -> fp16 pb (col is even: half2 per store)
    const int r0 = rowBase + mw * 64 + (lane >> 2);
    const int c0 = colBase + nw * 32 + (lane & 3) * 2;
#pragma unroll
    for (int i = 0; i < 4; i++)
#pragma unroll
        for (int nt = 0; nt < 4; nt++) {
            const int row = r0 + i * 16;
            const int col = c0 + nt * 8;
            __half2 lo = __floats2half2_rn(d[i][nt][0], d[i][nt][1]);
            __half2 hi = __floats2half2_rn(d[i][nt][2], d[i][nt][3]);
            *(__half2*)&g_pb16[(size_t)row * HH + col]       = lo;
            *(__half2*)&g_pb16[(size_t)(row + 8) * HH + col] = hi;
        }
}

// ---------------------------------------------------------------------------
// Kernel 3: e[b, m*S+s] = sum_h w2[h] * tanh(pb[b,s,h] + pm[b,m,h]).
// Warp per s; fp16 pb front-batched as half2 (MLP 8 x 128B).
// pm/w2 in even/odd split fp32 smem (conflict-free paired access).
// ---------------------------------------------------------------------------
__global__ __launch_bounds__(256)
void e_kernel(const float* __restrict__ w2)
{
    __shared__ float pmE[MM][HH / 2];
    __shared__ float pmO[MM][HH / 2];
    __shared__ float w2E[HH / 2];
    __shared__ float w2O[HH / 2];

    const int b   = blockIdx.y;
    const int tid = threadIdx.x;
    for (int i = tid; i < MM * HH; i += 256) {
        const int m = i >> 9, h = i & 511;
        const float v = g_pm[b * MM * HH + i];
        if (h & 1) pmO[m][h >> 1] = v; else pmE[m][h >> 1] = v;
    }
    for (int i = tid; i < HH; i += 256) {
        const float v = w2[i];
        if (i & 1) w2O[i >> 1] = v; else w2E[i >> 1] = v;
    }
    __syncthreads();

    const int warp = tid >> 5, lane = tid & 31;
    const int s = blockIdx.x * 8 + warp;
    const uint32_t* __restrict__ pb =
        (const uint32_t*)(g_pb16 + (size_t)(b * SS + s) * HH);

    uint32_t pv[8];
#pragma unroll
    for (int j = 0; j < 8; j++) pv[j] = pb[lane + j * 32];   // h pair = 2*(lane+j*32)

    float acc[MM];
#pragma unroll
    for (int m = 0; m < MM; m++) acc[m] = 0.f;

#pragma unroll
    for (int j = 0; j < 8; j++) {
        const int idx = lane + j * 32;
        const float2 p = __half22float2(*(__half2*)&pv[j]);
        const float wE = w2E[idx];
        const float wO = w2O[idx];
#pragma unroll
        for (int m = 0; m < MM; m++) {
            acc[m] = fmaf(wE, fast_tanh(p.x + pmE[m][idx]), acc[m]);
            acc[m] = fmaf(wO, fast_tanh(p.y + pmO[m][idx]), acc[m]);
        }
    }
#pragma unroll
    for (int m = 0; m < MM; m++)
#pragma unroll
        for (int o = 16; o; o >>= 1) acc[m] += __shfl_xor_sync(0xFFFFFFFFu, acc[m], o);

    if (lane == 0) {
#pragma unroll
        for (int m = 0; m < MM; m++) g_e[b * MM * SS + m * SS + s] = acc[m];
    }
}

// ---------------------------------------------------------------------------
// Kernel 4: softmax over 4096, *mask, renorm; writes g_as[b][s].
// ---------------------------------------------------------------------------
__global__ __launch_bounds__(1024)
void softmax_kernel(const float* __restrict__ face_mask, float* __restrict__ alpha)
{
    __shared__ float sred[32];
    __shared__ float asum[1024];
    const int b = blockIdx.x;
    const int tid = threadIdx.x;
    const int w = tid >> 5, l = tid & 31;
    const float* __restrict__ e = g_e + b * (MM * SS);

    float v[4];
    float mx = -CUDART_INF_F;
#pragma unroll
    for (int i = 0; i < 4; i++) { v[i] = e[tid + i * 1024]; mx = fmaxf(mx, v[i]); }

#pragma unroll
    for (int o = 16; o; o >>= 1) mx = fmaxf(mx, __shfl_xor_sync(0xFFFFFFFFu, mx, o));
    if (l == 0) sred[w] = mx;
    __syncthreads();
    if (tid < 32) {
        float t = sred[tid];
#pragma unroll
        for (int o = 16; o; o >>= 1) t = fmaxf(t, __shfl_xor_sync(0xFFFFFFFFu, t, o));
        if (tid == 0) sred[0] = t;
    }
    __syncthreads();
    mx = sred[0];
    __syncthreads();

    float sum = 0.f;
#pragma unroll
    for (int i = 0; i < 4; i++) { v[i] = __expf(v[i] - mx); sum += v[i]; }
#pragma unroll
    for (int o = 16; o; o >>= 1) sum += __shfl_xor_sync(0xFFFFFFFFu, sum, o);
    if (l == 0) sred[w] = sum;
    __syncthreads();
    if (tid < 32) {
        float t = sred[tid];
#pragma unroll
        for (int o = 16; o; o >>= 1) t += __shfl_xor_sync(0xFFFFFFFFu, t, o);
        if (tid == 0) sred[0] = t;
    }
    __syncthreads();
    const float Z = sred[0];
    __syncthreads();

    const float invZ = 1.f / Z;
    float msum = 0.f;
#pragma unroll
    for (int i = 0; i < 4; i++) {
        const int idx = tid + i * 1024;
        const float mk = face_mask[b * SS + (idx & 511)];
        v[i] = v[i] * invZ * mk;
        msum += v[i];
    }
#pragma unroll
    for (int o = 16; o; o >>= 1) msum += __shfl_xor_sync(0xFFFFFFFFu, msum, o);
    if (l == 0) sred[w] = msum;
    __syncthreads();
    if (tid < 32) {
        float t = sred[tid];
#pragma unroll
        for (int o = 16; o; o >>= 1) t += __shfl_xor_sync(0xFFFFFFFFu, t, o);
        if (tid == 0) sred[0] = t;
    }
    __syncthreads();
    const float inv = 1.f / (sred[0] + EPSF);

    float part = 0.f;
#pragma unroll
    for (int i = 0; i < 4; i++) {
        const float a = v[i] * inv;
        alpha[b * (MM * SS) + tid + i * 1024] = a;
        part += a;
    }
    asum[tid] = part;
    __syncthreads();
    if (tid < 512) g_as[b * SS + tid] = asum[tid] + asum[tid + 512];
}

// ---------------------------------------------------------------------------
// Kernel 5a: context partials. Grid (4, B).
// ---------------------------------------------------------------------------
__global__ __launch_bounds__(512)
void ctx_partial_kernel(const float* __restrict__ face)
{
    __shared__ float as_s[128];
    const int q = blockIdx.x;
    const int b = blockIdx.y;
    const int tid = threadIdx.x;

    if (tid < 128) as_s[tid] = g_as[b * SS + q * 128 + tid];
    __syncthreads();

    const float* __restrict__ fb = face + (size_t)b * SS * 512 + (size_t)q * 128 * 512;
    float c0 = 0.f, c1 = 0.f, c2 = 0.f, c3 = 0.f;
#pragma unroll 4
    for (int s = 0; s < 128; s += 4) {
        c0 = fmaf(as_s[s],     fb[(size_t)s * 512 + tid],       c0);
        c1 = fmaf(as_s[s + 1], fb[(size_t)(s + 1) * 512 + tid], c1);
        c2 = fmaf(as_s[s + 2], fb[(size_t)(s + 2) * 512 + tid], c2);
        c3 = fmaf(as_s[s + 3], fb[(size_t)(s + 3) * 512 + tid], c3);
    }
    g_cp[(b * 4 + q) * 512 + tid] = (c0 + c1) + (c2 + c3);
}

// ---------------------------------------------------------------------------
// Kernel 5b: sum the 4 partials -> ctx.
// ---------------------------------------------------------------------------
__global__ __launch_bounds__(512)
void ctx_reduce_kernel(float* __restrict__ ctx)
{
    const int b = blockIdx.x;
    const int tid = threadIdx.x;
    const float* __restrict__ p = &g_cp[b * 4 * 512 + tid];
    ctx[b * 512 + tid] = (p[0] + p[512]) + (p[1024] + p[1536]);
}

// ---------------------------------------------------------------------------
// Launch. Inputs: 0 fc, 1 img, 2 label, 3 memory, 4 face, 5 face_mask,
// 6 W1, 7 b1, 8 w2.  Output: alpha [B, M*S] then context [B, DF].
// ---------------------------------------------------------------------------
extern "C" void kernel_launch(void* const* d_in, const int* in_sizes, int n_in,
                              void* d_out, int out_size)
{
    const float* fc     = (const float*)d_in[0];
    const float* img    = (const float*)d_in[1];
    const float* label  = (const float*)d_in[2];
    const float* memory = (const float*)d_in[3];
    const float* face   = (const float*)d_in[4];
    const float* fmask  = (const float*)d_in[5];
    const float* W1     = (const float*)d_in[6];
    const float* b1     = (const float*)d_in[7];
    const float* w2     = (const float*)d_in[8];

    float* out   = (float*)d_out;
    float* alpha = out;                      // [B, M*S]
    float* ctx   = out + BB * MM * SS;       // [B, DF]

    cudaFuncSetAttribute(gemm_pb_mma, cudaFuncAttributeMaxDynamicSharedMemorySize, DYN_SMEM);

    setup_kernel<<<NB_PM + NB_W + NB_A, 256>>>(W1, memory, label, b1, face, fc, img);
    gemm_pb_mma<<<dim3(HH / GN, (BB * SS) / GM), 256, DYN_SMEM>>>();
    e_kernel<<<dim3(SS / 8, BB), 256>>>(w2);
    softmax_kernel<<<BB, 1024>>>(fmask, alpha);
    ctx_partial_kernel<<<dim3(4, BB), 512>>>(face);
    ctx_reduce_kernel<<<BB, 512>>>(ctx);
}